// round 1
// baseline (speedup 1.0000x reference)
#include <cuda_runtime.h>
#include <math.h>

// Problem constants
#define BB 512
#define TT 168
#define HH 512
#define GG 2048   // 4*H
#define WD 4

// ---------------- device scratch (no allocations allowed) ----------------
__device__ float g_h1[TT * BB * HH];   // layer-1 hidden sequence [t][b][h]
__device__ float g_h2[TT * BB * HH];   // layer-2 hidden sequence [t][b][h]
__device__ float g_c[BB * HH];         // running cell state (reused per layer)

// Permuted (gate-interleaved) weights: col' = 4*j + q, original col = q*512 + j
__device__ float g_U1p[HH * GG];
__device__ float g_U2p[HH * GG];
__device__ float g_W2p[HH * GG];
__device__ float g_W1p[GG];
__device__ float g_V1p[WD * GG];
__device__ float g_b1p[GG];
__device__ float g_V2p[WD * GG];
__device__ float g_b2p[GG];

// ---------------- prologue: permute weights to interleaved gate layout ----------------
__global__ void permute_kernel(const float* __restrict__ W1, const float* __restrict__ U1,
                               const float* __restrict__ V1, const float* __restrict__ b1,
                               const float* __restrict__ W2, const float* __restrict__ U2,
                               const float* __restrict__ V2, const float* __restrict__ b2) {
    int idx = blockIdx.x * blockDim.x + threadIdx.x;
    if (idx >= HH * GG) return;
    int k  = idx / GG;
    int gp = idx - k * GG;
    int go = (gp & 3) * HH + (gp >> 2);   // original column
    g_U1p[idx] = U1[k * GG + go];
    g_U2p[idx] = U2[k * GG + go];
    g_W2p[idx] = W2[k * GG + go];
    if (k == 0) {
        g_W1p[gp] = W1[go];
        g_b1p[gp] = b1[go];
        g_b2p[gp] = b2[go];
#pragma unroll
        for (int w = 0; w < WD; w++) {
            g_V1p[w * GG + gp] = V1[w * GG + go];
            g_V2p[w * GG + gp] = V2[w * GG + go];
        }
    }
}

// ---------------- step kernel: fused GEMM + LSTM pointwise ----------------
// Tile: BM=64 (batch) x BN=128 (gate cols) ; 256 threads, 4x8 per-thread microtile.
#define BM 64
#define BN 128
#define BK 16

__device__ __forceinline__ float sigf(float x) { return 1.0f / (1.0f + expf(-x)); }

template <int LAYER>
__global__ void __launch_bounds__(256) step_kernel(const float* __restrict__ inp, int t) {
    __shared__ float As[BK][BM];        // 4 KB
    __shared__ float Bs[BK][BN + 4];    // 8.25 KB
    __shared__ float Gs[BM][BN];        // 32 KB (gate staging for pointwise)

    const int tid = threadIdx.x;
    const int bn0 = blockIdx.x * BN;
    const int bm0 = blockIdx.y * BM;
    const int tm = (tid >> 4) * 4;      // 0..60
    const int tn = (tid & 15) * 8;      // 0..120

    const float* Umat  = (LAYER == 1) ? g_U1p : g_U2p;
    const float* hprev = (LAYER == 1) ? &g_h1[(t - 1) * BB * HH] : &g_h2[(t - 1) * BB * HH];
    const float* h1t   = &g_h1[t * BB * HH];
    float*       hout  = (LAYER == 1) ? &g_h1[t * BB * HH] : &g_h2[t * BB * HH];

    float acc[4][8];
#pragma unroll
    for (int i = 0; i < 4; i++)
#pragma unroll
        for (int j = 0; j < 8; j++) acc[i][j] = 0.0f;

    // ---- GEMM accumulation helper over a K=512 matrix pair ----
    auto gemm = [&](const float* __restrict__ A, const float* __restrict__ Bmat) {
        for (int k0 = 0; k0 < HH; k0 += BK) {
            __syncthreads();
            // load A tile: 64 rows x 16 k (one float4 per thread), store transposed
            {
                int r  = tid >> 2;            // 0..63
                int kq = (tid & 3) * 4;       // 0,4,8,12
                float4 a4 = *reinterpret_cast<const float4*>(&A[(bm0 + r) * HH + k0 + kq]);
                As[kq + 0][r] = a4.x;
                As[kq + 1][r] = a4.y;
                As[kq + 2][r] = a4.z;
                As[kq + 3][r] = a4.w;
            }
            // load B tile: 16 k x 128 n (two float4 per thread)
            {
#pragma unroll
                for (int u = 0; u < 2; u++) {
                    int e  = tid + u * 256;   // 0..511
                    int kk = e >> 5;          // 0..15
                    int nn = (e & 31) * 4;    // 0..124
                    float4 b4 = *reinterpret_cast<const float4*>(&Bmat[(k0 + kk) * GG + bn0 + nn]);
                    *reinterpret_cast<float4*>(&Bs[kk][nn]) = b4;
                }
            }
            __syncthreads();
#pragma unroll
            for (int kk = 0; kk < BK; kk++) {
                float a0 = As[kk][tm + 0];
                float a1 = As[kk][tm + 1];
                float a2 = As[kk][tm + 2];
                float a3 = As[kk][tm + 3];
                float b[8];
#pragma unroll
                for (int j = 0; j < 8; j++) b[j] = Bs[kk][tn + j];
#pragma unroll
                for (int j = 0; j < 8; j++) {
                    acc[0][j] += a0 * b[j];
                    acc[1][j] += a1 * b[j];
                    acc[2][j] += a2 * b[j];
                    acc[3][j] += a3 * b[j];
                }
            }
        }
    };

    if (t > 0) gemm(hprev, Umat);          // recurrent term (h_{t-1} == 0 at t=0)
    if (LAYER == 2) gemm(h1t, g_W2p);      // layer-2 input projection h1_t @ W2

    // ---- add per-(b,t) base: bias + weather@V (+ counts*W1 for layer 1) ----
#pragma unroll
    for (int mi = 0; mi < 4; mi++) {
        int bg = bm0 + tm + mi;
        const float* xr = inp + (bg * TT + t) * (WD + 1);
        float w0 = xr[0], w1 = xr[1], w2 = xr[2], w3 = xr[3];
        float cnt = xr[4];
#pragma unroll
        for (int ni = 0; ni < 8; ni++) {
            int g = bn0 + tn + ni;
            float base;
            if (LAYER == 1) {
                base = g_b1p[g] + cnt * g_W1p[g]
                     + w0 * g_V1p[0 * GG + g] + w1 * g_V1p[1 * GG + g]
                     + w2 * g_V1p[2 * GG + g] + w3 * g_V1p[3 * GG + g];
            } else {
                base = g_b2p[g]
                     + w0 * g_V2p[0 * GG + g] + w1 * g_V2p[1 * GG + g]
                     + w2 * g_V2p[2 * GG + g] + w3 * g_V2p[3 * GG + g];
            }
            acc[mi][ni] += base;
        }
    }

    // ---- stage gates to smem, then fused LSTM pointwise ----
    __syncthreads();
#pragma unroll
    for (int mi = 0; mi < 4; mi++)
#pragma unroll
        for (int ni = 0; ni < 8; ni++) Gs[tm + mi][tn + ni] = acc[mi][ni];
    __syncthreads();

    // This CTA owns hidden units j in [bn0/4, bn0/4 + 32) for batch rows [bm0, bm0+64)
#pragma unroll
    for (int u = 0; u < 8; u++) {
        int e  = tid + u * 256;       // 0..2047
        int bl = e >> 5;              // 0..63
        int jl = e & 31;              // 0..31
        float gi = Gs[bl][4 * jl + 0];
        float gf = Gs[bl][4 * jl + 1];
        float gg = Gs[bl][4 * jl + 2];
        float go = Gs[bl][4 * jl + 3];
        int bglob = bm0 + bl;
        int jglob = (bn0 >> 2) + jl;
        int cidx = bglob * HH + jglob;
        float cp = (t == 0) ? 0.0f : g_c[cidx];
        float c  = sigf(gf) * cp + sigf(gi) * tanhf(gg);
        float h  = sigf(go) * tanhf(c);
        g_c[cidx] = c;
        hout[bglob * HH + jglob] = h;
    }
}

// ---------------- final FC: out[b*T+t] = h2[t][b][:] . fc_w + fc_b ----------------
__global__ void fc_kernel(const float* __restrict__ fc_w, const float* __restrict__ fc_b,
                          float* __restrict__ out) {
    int warp = (blockIdx.x * blockDim.x + threadIdx.x) >> 5;
    int lane = threadIdx.x & 31;
    if (warp >= BB * TT) return;
    int b = warp / TT;
    int t = warp - b * TT;
    const float* h = &g_h2[t * BB * HH + b * HH];
    float s = 0.0f;
#pragma unroll
    for (int j = lane; j < HH; j += 32) s += h[j] * fc_w[j];
#pragma unroll
    for (int o = 16; o; o >>= 1) s += __shfl_xor_sync(0xFFFFFFFFu, s, o);
    if (lane == 0) out[warp] = s + fc_b[0];
}

// ---------------- launch ----------------
extern "C" void kernel_launch(void* const* d_in, const int* in_sizes, int n_in,
                              void* d_out, int out_size) {
    const float* inputs = (const float*)d_in[0];
    const float* W1 = (const float*)d_in[1];
    const float* U1 = (const float*)d_in[2];
    const float* V1 = (const float*)d_in[3];
    const float* b1 = (const float*)d_in[4];
    const float* W2 = (const float*)d_in[5];
    const float* U2 = (const float*)d_in[6];
    const float* V2 = (const float*)d_in[7];
    const float* b2 = (const float*)d_in[8];
    const float* fc_w = (const float*)d_in[9];
    const float* fc_b = (const float*)d_in[10];
    float* out = (float*)d_out;

    permute_kernel<<<(HH * GG + 255) / 256, 256>>>(W1, U1, V1, b1, W2, U2, V2, b2);

    dim3 grid(GG / BN, BB / BM);   // (16, 8) = 128 CTAs
    for (int t = 0; t < TT; t++) step_kernel<1><<<grid, 256>>>(inputs, t);
    for (int t = 0; t < TT; t++) step_kernel<2><<<grid, 256>>>(inputs, t);

    int nwarps = BB * TT;
    fc_kernel<<<(nwarps * 32 + 255) / 256, 256>>>(fc_w, fc_b, out);
}

// round 6
// speedup vs baseline: 1.9058x; 1.9058x over previous
#include <cuda_runtime.h>
#include <cuda_bf16.h>
#include <math.h>
#include <stdint.h>

#define BB 512
#define TT 168
#define HH 512
#define GG 2048   // 4*H
#define WD 4
#define BH (BB*HH)

// ---------------- device scratch ----------------
__device__ __align__(256) __nv_bfloat16 g_h1h[TT*BH];
__device__ __align__(256) __nv_bfloat16 g_h1l[TT*BH];
__device__ __align__(256) __nv_bfloat16 g_h2h[TT*BH];
__device__ __align__(256) __nv_bfloat16 g_h2l[TT*BH];
__device__ float g_c[BH];

// transposed + gate-interleaved weights, layout [n=2048][k=512] bf16 (hi/lo)
__device__ __align__(256) __nv_bfloat16 g_U1h[GG*HH], g_U1l[GG*HH];
__device__ __align__(256) __nv_bfloat16 g_U2h[GG*HH], g_U2l[GG*HH];
__device__ __align__(256) __nv_bfloat16 g_W2h[GG*HH], g_W2l[GG*HH];
__device__ float g_b1p[GG], g_b2p[GG], g_W1p[GG], g_V1p[WD*GG], g_V2p[WD*GG];

// ---------------- helpers ----------------
__device__ __forceinline__ uint32_t s2u(const void* p) {
    uint32_t a;
    asm("{ .reg .u64 t; cvta.to.shared.u64 t, %1; cvt.u32.u64 %0, t; }" : "=r"(a) : "l"(p));
    return a;
}
__device__ __forceinline__ void cpasync16(uint32_t dst, const void* src) {
    asm volatile("cp.async.cg.shared.global [%0], [%1], 16;" :: "r"(dst), "l"(src));
}
#define CP_COMMIT() asm volatile("cp.async.commit_group;")
#define CP_WAIT(n)  asm volatile("cp.async.wait_group %0;" :: "n"(n))
#define LDSM4(r0,r1,r2,r3,addr) \
    asm volatile("ldmatrix.sync.aligned.m8n8.x4.shared.b16 {%0,%1,%2,%3}, [%4];" \
        : "=r"(r0),"=r"(r1),"=r"(r2),"=r"(r3) : "r"(addr))

__device__ __forceinline__ void mma16816(float* c, const uint32_t* a, uint32_t b0, uint32_t b1) {
    asm volatile("mma.sync.aligned.m16n8k16.row.col.f32.bf16.bf16.f32 "
        "{%0,%1,%2,%3}, {%4,%5,%6,%7}, {%8,%9}, {%0,%1,%2,%3};"
        : "+f"(c[0]), "+f"(c[1]), "+f"(c[2]), "+f"(c[3])
        : "r"(a[0]), "r"(a[1]), "r"(a[2]), "r"(a[3]), "r"(b0), "r"(b1));
}

__device__ __forceinline__ float sigf(float x) { return 1.0f / (1.0f + __expf(-x)); }
__device__ __forceinline__ float tanhfast(float x) { return 1.0f - 2.0f / (1.0f + __expf(2.0f * x)); }

// ---------------- prologue: permute + transpose + bf16 hi/lo split ----------------
__global__ void prep_kernel(const float* __restrict__ W1, const float* __restrict__ U1,
                            const float* __restrict__ V1, const float* __restrict__ b1,
                            const float* __restrict__ W2, const float* __restrict__ U2,
                            const float* __restrict__ V2, const float* __restrict__ b2) {
    int idx = blockIdx.x * blockDim.x + threadIdx.x;
    if (idx >= HH * GG) return;
    int k  = idx >> 11;
    int gp = idx & (GG - 1);
    int go = (gp & 3) * HH + (gp >> 2);
    int dst = gp * HH + k;

    float u1 = U1[k * GG + go];
    __nv_bfloat16 h = __float2bfloat16(u1);
    g_U1h[dst] = h; g_U1l[dst] = __float2bfloat16(u1 - __bfloat162float(h));
    float u2 = U2[k * GG + go];
    h = __float2bfloat16(u2);
    g_U2h[dst] = h; g_U2l[dst] = __float2bfloat16(u2 - __bfloat162float(h));
    float w2 = W2[k * GG + go];
    h = __float2bfloat16(w2);
    g_W2h[dst] = h; g_W2l[dst] = __float2bfloat16(w2 - __bfloat162float(h));

    if (k == 0) {
        g_W1p[gp] = W1[go];
        g_b1p[gp] = b1[go];
        g_b2p[gp] = b2[go];
#pragma unroll
        for (int w = 0; w < WD; w++) {
            g_V1p[w * GG + gp] = V1[w * GG + go];
            g_V2p[w * GG + gp] = V2[w * GG + go];
        }
    }
}

// ---------------- step kernel: mma.sync GEMM + fused LSTM ----------------
// CTA tile M=64 (batch) x N=128 (gates). Grid (16, 8) = 128 CTAs. 256 threads.
#define BM 64
#define BN 128
#define BK 32
#define NS 3
#define ASTRIDE 80                       // padded row stride (bytes) for 64B rows
#define A_BYTES (BM*ASTRIDE)             // 5120
#define B_BYTES (BN*ASTRIDE)             // 10240
#define STAGE_BYTES (A_BYTES + B_BYTES)  // 15360
#define PAR_OFF 64
#define STG_OFF 4224
#define GSP 136                          // gate-staging row stride (floats)
#define SMEM_TOTAL (STG_OFF + NS*STAGE_BYTES)   // 50304

template <int LAYER>
__global__ void __launch_bounds__(256) step_kernel(const float* __restrict__ inp, int t) {
    extern __shared__ char smem[];
    const uint32_t sb = s2u(smem);
    const int tid = threadIdx.x, lane = tid & 31, wid = tid >> 5;
    const int bn0 = blockIdx.x * BN, bm0 = blockIdx.y * BM;
    const int wm = (wid & 1) * 32, wn = (wid >> 1) * 32;

    // packed per-column params: [col][8] = {b, W, V0, V1, V2, V3, pad, pad}
    float* sP = (float*)(smem + PAR_OFF);
    if (tid < BN) {
        int g = bn0 + tid;
        float* p = sP + tid * 8;
        if (LAYER == 1) {
            p[0] = g_b1p[g]; p[1] = g_W1p[g];
#pragma unroll
            for (int w = 0; w < 4; w++) p[2 + w] = g_V1p[w * GG + g];
        } else {
            p[0] = g_b2p[g]; p[1] = 0.0f;
#pragma unroll
            for (int w = 0; w < 4; w++) p[2 + w] = g_V2p[w * GG + g];
        }
        p[6] = 0.0f; p[7] = 0.0f;
    }

    // K segments (each K=512): 3-term hi/lo products
    const __nv_bfloat16 *segA[6], *segB[6];
    int ns = 0;
    if (LAYER == 1) {
        if (t > 0) {
            const __nv_bfloat16* ah = g_h1h + (size_t)(t - 1) * BH;
            const __nv_bfloat16* al = g_h1l + (size_t)(t - 1) * BH;
            segA[0] = ah; segB[0] = g_U1h;
            segA[1] = ah; segB[1] = g_U1l;
            segA[2] = al; segB[2] = g_U1h;
            ns = 3;
        }
    } else {
        if (t > 0) {
            const __nv_bfloat16* ah = g_h2h + (size_t)(t - 1) * BH;
            const __nv_bfloat16* al = g_h2l + (size_t)(t - 1) * BH;
            segA[ns] = ah; segB[ns] = g_U2h; ns++;
            segA[ns] = ah; segB[ns] = g_U2l; ns++;
            segA[ns] = al; segB[ns] = g_U2h; ns++;
        }
        const __nv_bfloat16* ah = g_h1h + (size_t)t * BH;
        const __nv_bfloat16* al = g_h1l + (size_t)t * BH;
        segA[ns] = ah; segB[ns] = g_W2h; ns++;
        segA[ns] = ah; segB[ns] = g_W2l; ns++;
        segA[ns] = al; segB[ns] = g_W2h; ns++;
    }
    const int ntiles = ns * (HH / BK);   // ns * 16

    float acc[2][4][4];
#pragma unroll
    for (int i = 0; i < 2; i++)
#pragma unroll
        for (int j = 0; j < 4; j++)
#pragma unroll
            for (int q = 0; q < 4; q++) acc[i][j][q] = 0.0f;

    auto load_stage = [&](int i, int s) {
        const int seg = i >> 4;
        const int kc = (i & 15) << 5;
        const __nv_bfloat16* Ab = segA[seg];
        const __nv_bfloat16* Bb = segB[seg];
        const uint32_t stA = sb + STG_OFF + s * STAGE_BYTES;
        const uint32_t stB = stA + A_BYTES;
        {   // A: 64 rows x 64B (1 x 16B per thread)
            int r = tid >> 2, c = tid & 3;
            cpasync16(stA + r * ASTRIDE + c * 16, Ab + (size_t)(bm0 + r) * HH + kc + c * 8);
        }
#pragma unroll
        for (int u = 0; u < 2; u++) {   // B: 128 rows x 64B (2 x 16B per thread)
            int e = tid + (u << 8);
            int r = e >> 2, c = e & 3;
            cpasync16(stB + r * ASTRIDE + c * 16, Bb + (size_t)(bn0 + r) * HH + kc + c * 8);
        }
    };

#pragma unroll 1
    for (int j = 0; j < NS - 1 && j < ntiles; j++) { load_stage(j, j); CP_COMMIT(); }

#pragma unroll 1
    for (int i = 0; i < ntiles; i++) {
        int pf = i + NS - 1;
        if (pf < ntiles) load_stage(pf, pf % NS);
        CP_COMMIT();
        CP_WAIT(NS - 1);
        __syncthreads();
        const uint32_t stA = sb + STG_OFF + (i % NS) * STAGE_BYTES;
        const uint32_t stB = stA + A_BYTES;
#pragma unroll
        for (int step = 0; step < 2; step++) {
            uint32_t a[2][4], b[2][4];
#pragma unroll
            for (int mt = 0; mt < 2; mt++)
                LDSM4(a[mt][0], a[mt][1], a[mt][2], a[mt][3],
                      stA + (wm + mt * 16 + (lane & 15)) * ASTRIDE + step * 32 + (lane >> 4) * 16);
#pragma unroll
            for (int np = 0; np < 2; np++)
                LDSM4(b[np][0], b[np][1], b[np][2], b[np][3],
                      stB + (wn + np * 16 + (lane & 15)) * ASTRIDE + step * 32 + (lane >> 4) * 16);
#pragma unroll
            for (int mt = 0; mt < 2; mt++)
#pragma unroll
                for (int nt = 0; nt < 4; nt++)
                    mma16816(acc[mt][nt], a[mt], b[nt >> 1][nt & 1], b[nt >> 1][(nt & 1) + 2]);
        }
        __syncthreads();
    }

    // ---- stage gates to smem (overlaps pipeline stages; all mma done) ----
    __syncthreads();
    float* Gs = (float*)(smem + STG_OFF);
#pragma unroll
    for (int mt = 0; mt < 2; mt++)
#pragma unroll
        for (int nt = 0; nt < 4; nt++) {
            int row = wm + mt * 16 + (lane >> 2);
            int col = wn + nt * 8 + (lane & 3) * 2;
            *(float2*)(Gs + row * GSP + col)       = make_float2(acc[mt][nt][0], acc[mt][nt][1]);
            *(float2*)(Gs + (row + 8) * GSP + col) = make_float2(acc[mt][nt][2], acc[mt][nt][3]);
        }
    __syncthreads();

    // ---- fused LSTM pointwise ----
    __nv_bfloat16* hh = (LAYER == 1 ? g_h1h : g_h2h) + (size_t)t * BH;
    __nv_bfloat16* hl = (LAYER == 1 ? g_h1l : g_h2l) + (size_t)t * BH;
#pragma unroll
    for (int u = 0; u < 8; u++) {
        int e = tid + (u << 8);
        int bl = e >> 5, jl = e & 31;
        int b = bm0 + bl;
        const float* xr = inp + ((size_t)b * TT + t) * (WD + 1);
        float w0 = xr[0], w1 = xr[1], w2 = xr[2], w3 = xr[3], cnt = xr[4];
        float4 g4 = *(float4*)(Gs + bl * GSP + jl * 4);
        float gr[4] = {g4.x, g4.y, g4.z, g4.w};
        float gv[4];
#pragma unroll
        for (int q = 0; q < 4; q++) {
            const float* p = sP + (jl * 4 + q) * 8;
            float4 p0 = *(const float4*)p;
            float4 p1 = *(const float4*)(p + 4);
            gv[q] = gr[q] + p0.x + cnt * p0.y + w0 * p0.z + w1 * p0.w + w2 * p1.x + w3 * p1.y;
        }
        int jg = (bn0 >> 2) + jl;
        int ci = b * HH + jg;
        float cp = (t > 0) ? g_c[ci] : 0.0f;
        float cc = sigf(gv[1]) * cp + sigf(gv[0]) * tanhfast(gv[2]);
        float hv = sigf(gv[3]) * tanhfast(cc);
        g_c[ci] = cc;
        __nv_bfloat16 hb = __float2bfloat16(hv);
        hh[ci] = hb;
        hl[ci] = __float2bfloat16(hv - __bfloat162float(hb));
    }
}

// ---------------- final FC ----------------
__global__ void fc_kernel(const float* __restrict__ fc_w, const float* __restrict__ fc_b,
                          float* __restrict__ out) {
    int warp = (blockIdx.x * blockDim.x + threadIdx.x) >> 5;
    int lane = threadIdx.x & 31;
    if (warp >= BB * TT) return;
    int b = warp / TT;
    int t = warp - b * TT;
    size_t base = (size_t)t * BH + (size_t)b * HH;
    float s = 0.0f;
#pragma unroll 4
    for (int j = lane; j < HH; j += 32)
        s += (__bfloat162float(g_h2h[base + j]) + __bfloat162float(g_h2l[base + j])) * fc_w[j];
#pragma unroll
    for (int o = 16; o; o >>= 1) s += __shfl_xor_sync(0xFFFFFFFFu, s, o);
    if (lane == 0) out[warp] = s + fc_b[0];
}

// ---------------- launch ----------------
extern "C" void kernel_launch(void* const* d_in, const int* in_sizes, int n_in,
                              void* d_out, int out_size) {
    const float* inputs = (const float*)d_in[0];
    const float* W1 = (const float*)d_in[1];
    const float* U1 = (const float*)d_in[2];
    const float* V1 = (const float*)d_in[3];
    const float* b1 = (const float*)d_in[4];
    const float* W2 = (const float*)d_in[5];
    const float* U2 = (const float*)d_in[6];
    const float* V2 = (const float*)d_in[7];
    const float* b2 = (const float*)d_in[8];
    const float* fc_w = (const float*)d_in[9];
    const float* fc_b = (const float*)d_in[10];
    float* out = (float*)d_out;

    cudaFuncSetAttribute(step_kernel<1>, cudaFuncAttributeMaxDynamicSharedMemorySize, SMEM_TOTAL);
    cudaFuncSetAttribute(step_kernel<2>, cudaFuncAttributeMaxDynamicSharedMemorySize, SMEM_TOTAL);

    prep_kernel<<<(HH * GG + 255) / 256, 256>>>(W1, U1, V1, b1, W2, U2, V2, b2);

    dim3 grid(GG / BN, BB / BM);   // (16, 8) = 128 CTAs
    for (int t = 0; t < TT; t++) step_kernel<1><<<grid, 256, SMEM_TOTAL>>>(inputs, t);
    for (int t = 0; t < TT; t++) step_kernel<2><<<grid, 256, SMEM_TOTAL>>>(inputs, t);

    int nwarps = BB * TT;
    fc_kernel<<<(nwarps * 32 + 255) / 256, 256>>>(fc_w, fc_b, out);
}

// round 8
// speedup vs baseline: 3.3513x; 1.7585x over previous
#include <cuda_runtime.h>
#include <cuda_bf16.h>
#include <math.h>
#include <stdint.h>

#define BB 512
#define TT 168
#define HH 512
#define GG 2048   // 4*H
#define WD 4
#define BH (BB*HH)

// ---------------- device scratch ----------------
__device__ __align__(256) __nv_bfloat16 g_h1h[TT*BH];
__device__ __align__(256) __nv_bfloat16 g_h1l[TT*BH];
__device__ __align__(256) __nv_bfloat16 g_h2h[TT*BH];
__device__ __align__(256) __nv_bfloat16 g_h2l[TT*BH];
__device__ float g_c[BH];

// transposed + gate-interleaved weights, layout [n=2048][k=512] bf16 (hi/lo)
__device__ __align__(256) __nv_bfloat16 g_U1h[GG*HH], g_U1l[GG*HH];
__device__ __align__(256) __nv_bfloat16 g_U2h[GG*HH], g_U2l[GG*HH];
__device__ __align__(256) __nv_bfloat16 g_W2h[GG*HH], g_W2l[GG*HH];
__device__ float g_b1p[GG], g_b2p[GG], g_W1p[GG], g_V1p[WD*GG], g_V2p[WD*GG];

// ---------------- helpers ----------------
__device__ __forceinline__ uint32_t s2u(const void* p) {
    uint32_t a;
    asm("{ .reg .u64 t; cvta.to.shared.u64 t, %1; cvt.u32.u64 %0, t; }" : "=r"(a) : "l"(p));
    return a;
}
__device__ __forceinline__ void cpasync16(uint32_t dst, const void* src) {
    asm volatile("cp.async.cg.shared.global [%0], [%1], 16;" :: "r"(dst), "l"(src));
}
#define CP_COMMIT() asm volatile("cp.async.commit_group;")
#define CP_WAIT(n)  asm volatile("cp.async.wait_group %0;" :: "n"(n))
#define LDSM4(r0,r1,r2,r3,addr) \
    asm volatile("ldmatrix.sync.aligned.m8n8.x4.shared.b16 {%0,%1,%2,%3}, [%4];" \
        : "=r"(r0),"=r"(r1),"=r"(r2),"=r"(r3) : "r"(addr))

__device__ __forceinline__ void mma16816(float* c, const uint32_t* a, uint32_t b0, uint32_t b1) {
    asm volatile("mma.sync.aligned.m16n8k16.row.col.f32.bf16.bf16.f32 "
        "{%0,%1,%2,%3}, {%4,%5,%6,%7}, {%8,%9}, {%0,%1,%2,%3};"
        : "+f"(c[0]), "+f"(c[1]), "+f"(c[2]), "+f"(c[3])
        : "r"(a[0]), "r"(a[1]), "r"(a[2]), "r"(a[3]), "r"(b0), "r"(b1));
}

__device__ __forceinline__ float sigf(float x) { return 1.0f / (1.0f + __expf(-x)); }
__device__ __forceinline__ float tanhfast(float x) { return 1.0f - 2.0f / (1.0f + __expf(2.0f * x)); }

// ---------------- prologue: permute + transpose + bf16 hi/lo split ----------------
__global__ void prep_kernel(const float* __restrict__ W1, const float* __restrict__ U1,
                            const float* __restrict__ V1, const float* __restrict__ b1,
                            const float* __restrict__ W2, const float* __restrict__ U2,
                            const float* __restrict__ V2, const float* __restrict__ b2) {
    int idx = blockIdx.x * blockDim.x + threadIdx.x;
    if (idx >= HH * GG) return;
    int k  = idx >> 11;
    int gp = idx & (GG - 1);
    int go = (gp & 3) * HH + (gp >> 2);
    int dst = gp * HH + k;

    float u1 = U1[k * GG + go];
    __nv_bfloat16 h = __float2bfloat16(u1);
    g_U1h[dst] = h; g_U1l[dst] = __float2bfloat16(u1 - __bfloat162float(h));
    float u2 = U2[k * GG + go];
    h = __float2bfloat16(u2);
    g_U2h[dst] = h; g_U2l[dst] = __float2bfloat16(u2 - __bfloat162float(h));
    float w2 = W2[k * GG + go];
    h = __float2bfloat16(w2);
    g_W2h[dst] = h; g_W2l[dst] = __float2bfloat16(w2 - __bfloat162float(h));

    if (k == 0) {
        g_W1p[gp] = W1[go];
        g_b1p[gp] = b1[go];
        g_b2p[gp] = b2[go];
#pragma unroll
        for (int w = 0; w < WD; w++) {
            g_V1p[w * GG + gp] = V1[w * GG + go];
            g_V2p[w * GG + gp] = V2[w * GG + go];
        }
    }
}

// ---------------- step kernel ----------------
// CTA tile M=64 (batch) x N=128 (gates), BK=64, 3 hi/lo terms per chunk.
// Grid (16, 8) = 128 CTAs, 256 threads (2x4 warps of 32x32).
#define BM 64
#define BN 128
#define NS 3
// stage layout: Ah(64x128B) Al(64x128B) Bh(128x128B) Bl(128x128B)
#define OA_H 0
#define OA_L 8192
#define OB_H 16384
#define OB_L 32768
#define STAGE_BYTES 49152
#define PAR_OFF 64
#define STG_OFF 4224
#define GSP 136
#define SMEM_TOTAL (STG_OFF + NS*STAGE_BYTES)   // 151680
// swizzled offset within a tile: row r (128B), 16B-column c (0..7)
#define TILE_OFF(r, c) (((r) << 7) + ((uint32_t)((c) ^ ((r) & 7)) << 4))

template <int LAYER>
__global__ void __launch_bounds__(256, 1) step_kernel(const float* __restrict__ inp, int t) {
    extern __shared__ char smem[];
    const uint32_t sb = s2u(smem);
    const int tid = threadIdx.x, lane = tid & 31, wid = tid >> 5;
    const int bn0 = blockIdx.x * BN, bm0 = blockIdx.y * BM;
    const int wm = (wid & 1) * 32, wn = (wid >> 1) * 32;

    // packed per-column params: [col][8] = {b, W, V0, V1, V2, V3, pad, pad}
    float* sP = (float*)(smem + PAR_OFF);
    if (tid < BN) {
        int g = bn0 + tid;
        float* p = sP + tid * 8;
        if (LAYER == 1) {
            p[0] = g_b1p[g]; p[1] = g_W1p[g];
#pragma unroll
            for (int w = 0; w < 4; w++) p[2 + w] = g_V1p[w * GG + g];
        } else {
            p[0] = g_b2p[g]; p[1] = 0.0f;
#pragma unroll
            for (int w = 0; w < 4; w++) p[2 + w] = g_V2p[w * GG + g];
        }
        p[6] = 0.0f; p[7] = 0.0f;
    }

    // K blocks (each K=512): A hi/lo + B hi/lo
    const __nv_bfloat16 *sAh[2], *sAl[2], *sBh[2], *sBl[2];
    int nblk = 0;
    if (LAYER == 1) {
        if (t > 0) {
            sAh[0] = g_h1h + (size_t)(t - 1) * BH; sAl[0] = g_h1l + (size_t)(t - 1) * BH;
            sBh[0] = g_U1h; sBl[0] = g_U1l;
            nblk = 1;
        }
    } else {
        if (t > 0) {
            sAh[nblk] = g_h2h + (size_t)(t - 1) * BH; sAl[nblk] = g_h2l + (size_t)(t - 1) * BH;
            sBh[nblk] = g_U2h; sBl[nblk] = g_U2l;
            nblk++;
        }
        sAh[nblk] = g_h1h + (size_t)t * BH; sAl[nblk] = g_h1l + (size_t)t * BH;
        sBh[nblk] = g_W2h; sBl[nblk] = g_W2l;
        nblk++;
    }
    const int nch = nblk * 8;   // BK=64 chunks

    float acc[2][4][4];
#pragma unroll
    for (int i = 0; i < 2; i++)
#pragma unroll
        for (int j = 0; j < 4; j++)
#pragma unroll
            for (int q = 0; q < 4; q++) acc[i][j][q] = 0.0f;

    auto load_stage = [&](int chunk, int stg) {
        const int blk = chunk >> 3;
        const int kc = (chunk & 7) << 6;
        const uint32_t base = sb + STG_OFF + stg * STAGE_BYTES;
        const __nv_bfloat16 *pAh = sAh[blk], *pAl = sAl[blk];
        const __nv_bfloat16 *pBh = sBh[blk], *pBl = sBl[blk];
#pragma unroll
        for (int i = 0; i < 2; i++) {        // A: 64 rows x 128B, hi+lo
            int e = tid + (i << 8); int r = e >> 3, q = e & 7;
            uint32_t off = TILE_OFF(r, q);
            size_t src = (size_t)(bm0 + r) * HH + kc + q * 8;
            cpasync16(base + OA_H + off, pAh + src);
            cpasync16(base + OA_L + off, pAl + src);
        }
#pragma unroll
        for (int i = 0; i < 4; i++) {        // B: 128 rows x 128B, hi+lo
            int e = tid + (i << 8); int r = e >> 3, q = e & 7;
            uint32_t off = TILE_OFF(r, q);
            size_t src = (size_t)(bn0 + r) * HH + kc + q * 8;
            cpasync16(base + OB_H + off, pBh + src);
            cpasync16(base + OB_L + off, pBl + src);
        }
    };

#pragma unroll 1
    for (int j = 0; j < NS - 1 && j < nch; j++) { load_stage(j, j); CP_COMMIT(); }

#pragma unroll 1
    for (int c = 0; c < nch; c++) {
        CP_WAIT(NS - 2);
        __syncthreads();
        int pf = c + NS - 1;
        if (pf < nch) load_stage(pf, pf % NS);
        CP_COMMIT();
        const uint32_t stg = sb + STG_OFF + (c % NS) * STAGE_BYTES;
#pragma unroll
        for (int s = 0; s < 4; s++) {
            const uint32_t ccol = (s << 1) + (lane >> 4);
            uint32_t ah[2][4], al[2][4], bh[2][4], bl[2][4];
#pragma unroll
            for (int mt = 0; mt < 2; mt++) {
                int row = wm + mt * 16 + (lane & 15);
                uint32_t off = TILE_OFF(row, ccol);
                LDSM4(ah[mt][0], ah[mt][1], ah[mt][2], ah[mt][3], stg + OA_H + off);
                LDSM4(al[mt][0], al[mt][1], al[mt][2], al[mt][3], stg + OA_L + off);
            }
#pragma unroll
            for (int np = 0; np < 2; np++) {
                int row = wn + np * 16 + (lane & 15);
                uint32_t off = TILE_OFF(row, ccol);
                LDSM4(bh[np][0], bh[np][1], bh[np][2], bh[np][3], stg + OB_H + off);
                LDSM4(bl[np][0], bl[np][1], bl[np][2], bl[np][3], stg + OB_L + off);
            }
#pragma unroll
            for (int mt = 0; mt < 2; mt++)
#pragma unroll
                for (int nt = 0; nt < 4; nt++) {
                    uint32_t b0 = bh[nt >> 1][nt & 1], b1 = bh[nt >> 1][(nt & 1) + 2];
                    mma16816(acc[mt][nt], ah[mt], b0, b1);
                    mma16816(acc[mt][nt], al[mt], b0, b1);
                    mma16816(acc[mt][nt], ah[mt], bl[nt >> 1][nt & 1], bl[nt >> 1][(nt & 1) + 2]);
                }
        }
    }

    // ---- stage gates to smem ----
    __syncthreads();
    float* Gs = (float*)(smem + STG_OFF);
#pragma unroll
    for (int mt = 0; mt < 2; mt++)
#pragma unroll
        for (int nt = 0; nt < 4; nt++) {
            int row = wm + mt * 16 + (lane >> 2);
            int col = wn + nt * 8 + (lane & 3) * 2;
            *(float2*)(Gs + row * GSP + col)       = make_float2(acc[mt][nt][0], acc[mt][nt][1]);
            *(float2*)(Gs + (row + 8) * GSP + col) = make_float2(acc[mt][nt][2], acc[mt][nt][3]);
        }
    __syncthreads();

    // ---- fused LSTM pointwise ----
    __nv_bfloat16* hh = (LAYER == 1 ? g_h1h : g_h2h) + (size_t)t * BH;
    __nv_bfloat16* hl = (LAYER == 1 ? g_h1l : g_h2l) + (size_t)t * BH;
#pragma unroll
    for (int u = 0; u < 8; u++) {
        int e = tid + (u << 8);
        int bl_ = e >> 5, jl = e & 31;
        int b = bm0 + bl_;
        const float* xr = inp + ((size_t)b * TT + t) * (WD + 1);
        float w0 = xr[0], w1 = xr[1], w2 = xr[2], w3 = xr[3], cnt = xr[4];
        float4 g4 = *(float4*)(Gs + bl_ * GSP + jl * 4);
        float gr[4] = {g4.x, g4.y, g4.z, g4.w};
        float gv[4];
#pragma unroll
        for (int q = 0; q < 4; q++) {
            const float* p = sP + (jl * 4 + q) * 8;
            float4 p0 = *(const float4*)p;
            float4 p1 = *(const float4*)(p + 4);
            gv[q] = gr[q] + p0.x + cnt * p0.y + w0 * p0.z + w1 * p0.w + w2 * p1.x + w3 * p1.y;
        }
        int jg = (bn0 >> 2) + jl;
        int ci = b * HH + jg;
        float cp = (t > 0) ? g_c[ci] : 0.0f;
        float cc = sigf(gv[1]) * cp + sigf(gv[0]) * tanhfast(gv[2]);
        float hv = sigf(gv[3]) * tanhfast(cc);
        g_c[ci] = cc;
        __nv_bfloat16 hb = __float2bfloat16(hv);
        hh[ci] = hb;
        hl[ci] = __float2bfloat16(hv - __bfloat162float(hb));
    }
}

// ---------------- final FC ----------------
__global__ void fc_kernel(const float* __restrict__ fc_w, const float* __restrict__ fc_b,
                          float* __restrict__ out) {
    int warp = (blockIdx.x * blockDim.x + threadIdx.x) >> 5;
    int lane = threadIdx.x & 31;
    if (warp >= BB * TT) return;
    int b = warp / TT;
    int t = warp - b * TT;
    size_t base = (size_t)t * BH + (size_t)b * HH;
    float s = 0.0f;
#pragma unroll 4
    for (int j = lane; j < HH; j += 32)
        s += (__bfloat162float(g_h2h[base + j]) + __bfloat162float(g_h2l[base + j])) * fc_w[j];
#pragma unroll
    for (int o = 16; o; o >>= 1) s += __shfl_xor_sync(0xFFFFFFFFu, s, o);
    if (lane == 0) out[warp] = s + fc_b[0];
}

// ---------------- launch ----------------
extern "C" void kernel_launch(void* const* d_in, const int* in_sizes, int n_in,
                              void* d_out, int out_size) {
    const float* inputs = (const float*)d_in[0];
    const float* W1 = (const float*)d_in[1];
    const float* U1 = (const float*)d_in[2];
    const float* V1 = (const float*)d_in[3];
    const float* b1 = (const float*)d_in[4];
    const float* W2 = (const float*)d_in[5];
    const float* U2 = (const float*)d_in[6];
    const float* V2 = (const float*)d_in[7];
    const float* b2 = (const float*)d_in[8];
    const float* fc_w = (const float*)d_in[9];
    const float* fc_b = (const float*)d_in[10];
    float* out = (float*)d_out;

    cudaFuncSetAttribute(step_kernel<1>, cudaFuncAttributeMaxDynamicSharedMemorySize, SMEM_TOTAL);
    cudaFuncSetAttribute(step_kernel<2>, cudaFuncAttributeMaxDynamicSharedMemorySize, SMEM_TOTAL);

    prep_kernel<<<(HH * GG + 255) / 256, 256>>>(W1, U1, V1, b1, W2, U2, V2, b2);

    dim3 grid(GG / BN, BB / BM);   // (16, 8) = 128 CTAs
    for (int t = 0; t < TT; t++) step_kernel<1><<<grid, 256, SMEM_TOTAL>>>(inputs, t);
    for (int t = 0; t < TT; t++) step_kernel<2><<<grid, 256, SMEM_TOTAL>>>(inputs, t);

    int nwarps = BB * TT;
    fc_kernel<<<(nwarps * 32 + 255) / 256, 256>>>(fc_w, fc_b, out);
}

// round 11
// speedup vs baseline: 3.4201x; 1.0205x over previous
#include <cuda_runtime.h>
#include <cuda_bf16.h>
#include <math.h>
#include <stdint.h>

#define BB 512
#define TT 168
#define HH 512
#define GG 2048   // 4*H
#define WD 4
#define BH (BB*HH)
#define NCTA 256

// ---------------- device scratch ----------------
__device__ __align__(256) __nv_bfloat16 g_h1h[TT*BH];
__device__ __align__(256) __nv_bfloat16 g_h1l[TT*BH];
__device__ __align__(256) __nv_bfloat16 g_h2h[TT*BH];
__device__ __align__(256) __nv_bfloat16 g_h2l[TT*BH];

// transposed + gate-interleaved weights, layout [n=2048][k=512] bf16 (hi/lo)
__device__ __align__(256) __nv_bfloat16 g_U1h[GG*HH], g_U1l[GG*HH];
__device__ __align__(256) __nv_bfloat16 g_U2h[GG*HH], g_U2l[GG*HH];
__device__ __align__(256) __nv_bfloat16 g_W2h[GG*HH], g_W2l[GG*HH];
__device__ float g_b1p[GG], g_b2p[GG], g_W1p[GG], g_V1p[WD*GG], g_V2p[WD*GG];
__device__ unsigned g_bar;

// ---------------- helpers ----------------
__device__ __forceinline__ uint32_t s2u(const void* p) {
    uint32_t a;
    asm("{ .reg .u64 t; cvta.to.shared.u64 t, %1; cvt.u32.u64 %0, t; }" : "=r"(a) : "l"(p));
    return a;
}
__device__ __forceinline__ void cpasync16(uint32_t dst, const void* src) {
    asm volatile("cp.async.cg.shared.global [%0], [%1], 16;" :: "r"(dst), "l"(src));
}
#define CP_COMMIT() asm volatile("cp.async.commit_group;")
#define CP_WAIT(n)  asm volatile("cp.async.wait_group %0;" :: "n"(n))
#define LDSM4(r0,r1,r2,r3,addr) \
    asm volatile("ldmatrix.sync.aligned.m8n8.x4.shared.b16 {%0,%1,%2,%3}, [%4];" \
        : "=r"(r0),"=r"(r1),"=r"(r2),"=r"(r3) : "r"(addr))

__device__ __forceinline__ void mma16816(float* c, const uint32_t* a, uint32_t b0, uint32_t b1) {
    asm volatile("mma.sync.aligned.m16n8k16.row.col.f32.bf16.bf16.f32 "
        "{%0,%1,%2,%3}, {%4,%5,%6,%7}, {%8,%9}, {%0,%1,%2,%3};"
        : "+f"(c[0]), "+f"(c[1]), "+f"(c[2]), "+f"(c[3])
        : "r"(a[0]), "r"(a[1]), "r"(a[2]), "r"(a[3]), "r"(b0), "r"(b1));
}

__device__ __forceinline__ float sigf(float x) { return 1.0f / (1.0f + __expf(-x)); }
__device__ __forceinline__ float tanhfast(float x) { return 1.0f - 2.0f / (1.0f + __expf(2.0f * x)); }

// device-wide barrier: all NCTA CTAs are co-resident by construction
__device__ __forceinline__ void grid_barrier(unsigned goal) {
    __syncthreads();
    if (threadIdx.x == 0) {
        __threadfence();
        atomicAdd(&g_bar, 1u);
        while (atomicAdd(&g_bar, 0u) < goal) __nanosleep(64);
        __threadfence();
    }
    __syncthreads();
}

// ---------------- prologue: permute + transpose + bf16 hi/lo split ----------------
__global__ void prep_kernel(const float* __restrict__ W1, const float* __restrict__ U1,
                            const float* __restrict__ V1, const float* __restrict__ b1,
                            const float* __restrict__ W2, const float* __restrict__ U2,
                            const float* __restrict__ V2, const float* __restrict__ b2) {
    int idx = blockIdx.x * blockDim.x + threadIdx.x;
    if (idx == 0) g_bar = 0u;
    if (idx >= HH * GG) return;
    int k  = idx >> 11;
    int gp = idx & (GG - 1);
    int go = (gp & 3) * HH + (gp >> 2);
    int dst = gp * HH + k;

    float u1 = U1[k * GG + go];
    __nv_bfloat16 h = __float2bfloat16(u1);
    g_U1h[dst] = h; g_U1l[dst] = __float2bfloat16(u1 - __bfloat162float(h));
    float u2 = U2[k * GG + go];
    h = __float2bfloat16(u2);
    g_U2h[dst] = h; g_U2l[dst] = __float2bfloat16(u2 - __bfloat162float(h));
    float w2 = W2[k * GG + go];
    h = __float2bfloat16(w2);
    g_W2h[dst] = h; g_W2l[dst] = __float2bfloat16(w2 - __bfloat162float(h));

    if (k == 0) {
        g_W1p[gp] = W1[go];
        g_b1p[gp] = b1[go];
        g_b2p[gp] = b2[go];
#pragma unroll
        for (int w = 0; w < WD; w++) {
            g_V1p[w * GG + gp] = V1[w * GG + go];
            g_V2p[w * GG + gp] = V2[w * GG + go];
        }
    }
}

// ---------------- persistent LSTM kernel ----------------
// CTA tile M=64 (batch) x N=64 (gates), BK=64, 3 hi/lo terms per chunk.
// Grid (32, 8) = 256 CTAs, 128 threads (2x2 warps of 32x32). 2 CTAs/SM.
#define NS 3
#define OA_H 0
#define OA_L 8192
#define OB_H 16384
#define OB_L 24576
#define STAGE_BYTES 32768
#define STG_OFF 2176
#define GSP 68
#define SMEM_TOTAL (STG_OFF + NS*STAGE_BYTES)   // 100480
#define TILE_OFF(r, c) (((r) << 7) + ((uint32_t)(((c) ^ ((r) & 7)) & 7) << 4))

__global__ void __launch_bounds__(128, 2) lstm_kernel(const float* __restrict__ inp) {
    extern __shared__ char smem[];
    const uint32_t sb = s2u(smem);
    const int tid = threadIdx.x, lane = tid & 31, wid = tid >> 5;
    const int bn0 = blockIdx.x * 64, bm0 = blockIdx.y * 64;
    const int wm = (wid & 1) * 32, wn = (wid >> 1) * 32;
    float* sP = (float*)(smem + 64);
    float* Gs = (float*)(smem + STG_OFF);
    unsigned goal = 0;

#pragma unroll 1
    for (int layer = 1; layer <= 2; layer++) {
        // per-column epilogue params: [col][8] = {b, W, V0..V3, pad, pad}
        if (tid < 64) {
            int g = bn0 + tid;
            float* p = sP + tid * 8;
            if (layer == 1) {
                p[0] = g_b1p[g]; p[1] = g_W1p[g];
#pragma unroll
                for (int w = 0; w < 4; w++) p[2 + w] = g_V1p[w * GG + g];
            } else {
                p[0] = g_b2p[g]; p[1] = 0.0f;
#pragma unroll
                for (int w = 0; w < 4; w++) p[2 + w] = g_V2p[w * GG + g];
            }
            p[6] = 0.0f; p[7] = 0.0f;
        }
        float creg[8];
#pragma unroll
        for (int u = 0; u < 8; u++) creg[u] = 0.0f;

        __nv_bfloat16* Hh = (layer == 1) ? g_h1h : g_h2h;
        __nv_bfloat16* Hl = (layer == 1) ? g_h1l : g_h2l;
        const __nv_bfloat16* Uh = (layer == 1) ? g_U1h : g_U2h;
        const __nv_bfloat16* Ul = (layer == 1) ? g_U1l : g_U2l;

#pragma unroll 1
        for (int t = 0; t < TT; t++) {
            const __nv_bfloat16 *sAh[2], *sAl[2], *sBh[2], *sBl[2];
            int nblk = 0;
            if (t > 0) {
                sAh[0] = Hh + (size_t)(t - 1) * BH; sAl[0] = Hl + (size_t)(t - 1) * BH;
                sBh[0] = Uh; sBl[0] = Ul;
                nblk = 1;
            }
            if (layer == 2) {
                sAh[nblk] = g_h1h + (size_t)t * BH; sAl[nblk] = g_h1l + (size_t)t * BH;
                sBh[nblk] = g_W2h; sBl[nblk] = g_W2l;
                nblk++;
            }
            const int nch = nblk * 8;

            float acc[2][4][4];
#pragma unroll
            for (int i = 0; i < 2; i++)
#pragma unroll
                for (int j = 0; j < 4; j++)
#pragma unroll
                    for (int q = 0; q < 4; q++) acc[i][j][q] = 0.0f;

            if (nch) {
                auto load_stage = [&](int chunk, int stg) {
                    const int blk = chunk >> 3;
                    const int kc = (chunk & 7) << 6;
                    const uint32_t base = sb + STG_OFF + stg * STAGE_BYTES;
                    const __nv_bfloat16 *pAh = sAh[blk], *pAl = sAl[blk];
                    const __nv_bfloat16 *pBh = sBh[blk], *pBl = sBl[blk];
#pragma unroll
                    for (int i = 0; i < 4; i++) {      // A: 64 rows x 128B, hi+lo
                        int e = tid + (i << 7); int r = e >> 3, q = e & 7;
                        uint32_t off = TILE_OFF(r, q);
                        size_t src = (size_t)(bm0 + r) * HH + kc + q * 8;
                        cpasync16(base + OA_H + off, pAh + src);
                        cpasync16(base + OA_L + off, pAl + src);
                    }
#pragma unroll
                    for (int i = 0; i < 4; i++) {      // B: 64 rows x 128B, hi+lo
                        int e = tid + (i << 7); int r = e >> 3, q = e & 7;
                        uint32_t off = TILE_OFF(r, q);
                        size_t src = (size_t)(bn0 + r) * HH + kc + q * 8;
                        cpasync16(base + OB_H + off, pBh + src);
                        cpasync16(base + OB_L + off, pBl + src);
                    }
                };

#pragma unroll 1
                for (int j = 0; j < NS - 1 && j < nch; j++) { load_stage(j, j); CP_COMMIT(); }

#pragma unroll 1
                for (int c = 0; c < nch; c++) {
                    CP_WAIT(NS - 2);
                    __syncthreads();
                    int pf = c + NS - 1;
                    if (pf < nch) load_stage(pf, pf % NS);
                    CP_COMMIT();
                    const uint32_t stg = sb + STG_OFF + (c % NS) * STAGE_BYTES;
#pragma unroll
                    for (int s = 0; s < 4; s++) {
                        const uint32_t ccol = (s << 1) + (lane >> 4);
                        uint32_t ah[2][4], al[2][4], bh[2][4], bl[2][4];
#pragma unroll
                        for (int mt = 0; mt < 2; mt++) {
                            int row = wm + mt * 16 + (lane & 15);
                            uint32_t off = TILE_OFF(row, ccol);
                            LDSM4(ah[mt][0], ah[mt][1], ah[mt][2], ah[mt][3], stg + OA_H + off);
                            LDSM4(al[mt][0], al[mt][1], al[mt][2], al[mt][3], stg + OA_L + off);
                        }
#pragma unroll
                        for (int np = 0; np < 2; np++) {
                            int row = wn + np * 16 + (lane & 15);
                            uint32_t off = TILE_OFF(row, ccol);
                            LDSM4(bh[np][0], bh[np][1], bh[np][2], bh[np][3], stg + OB_H + off);
                            LDSM4(bl[np][0], bl[np][1], bl[np][2], bl[np][3], stg + OB_L + off);
                        }
#pragma unroll
                        for (int mt = 0; mt < 2; mt++)
#pragma unroll
                            for (int nt = 0; nt < 4; nt++) {
                                uint32_t b0 = bh[nt >> 1][nt & 1], b1 = bh[nt >> 1][(nt & 1) + 2];
                                mma16816(acc[mt][nt], ah[mt], b0, b1);
                                mma16816(acc[mt][nt], al[mt], b0, b1);
                                mma16816(acc[mt][nt], ah[mt], bl[nt >> 1][nt & 1], bl[nt >> 1][(nt & 1) + 2]);
                            }
                    }
                }
            }

            // ---- stage gates to smem (reuses stage0; all loads drained) ----
            __syncthreads();
#pragma unroll
            for (int mt = 0; mt < 2; mt++)
#pragma unroll
                for (int nt = 0; nt < 4; nt++) {
                    int row = wm + mt * 16 + (lane >> 2);
                    int col = wn + nt * 8 + (lane & 3) * 2;
                    *(float2*)(Gs + row * GSP + col)       = make_float2(acc[mt][nt][0], acc[mt][nt][1]);
                    *(float2*)(Gs + (row + 8) * GSP + col) = make_float2(acc[mt][nt][2], acc[mt][nt][3]);
                }
            __syncthreads();

            // ---- fused LSTM pointwise (c lives in registers across t) ----
            __nv_bfloat16* hh = Hh + (size_t)t * BH;
            __nv_bfloat16* hl = Hl + (size_t)t * BH;
#pragma unroll
            for (int u = 0; u < 8; u++) {
                int e = tid + (u << 7);
                int bl_ = e >> 4, jl = e & 15;
                int b = bm0 + bl_;
                const float* xr = inp + ((size_t)b * TT + t) * (WD + 1);
                float w0 = xr[0], w1 = xr[1], w2 = xr[2], w3 = xr[3], cnt = xr[4];
                float4 g4 = *(float4*)(Gs + bl_ * GSP + jl * 4);
                float gr[4] = {g4.x, g4.y, g4.z, g4.w};
                float gv[4];
#pragma unroll
                for (int q = 0; q < 4; q++) {
                    const float* p = sP + (jl * 4 + q) * 8;
                    float4 p0 = *(const float4*)p;
                    float4 p1 = *(const float4*)(p + 4);
                    gv[q] = gr[q] + p0.x + cnt * p0.y + w0 * p0.z + w1 * p0.w + w2 * p1.x + w3 * p1.y;
                }
                float cc = sigf(gv[1]) * creg[u] + sigf(gv[0]) * tanhfast(gv[2]);
                float hv = sigf(gv[3]) * tanhfast(cc);
                creg[u] = cc;
                int ci = b * HH + (bn0 >> 2) + jl;
                __nv_bfloat16 hb = __float2bfloat16(hv);
                hh[ci] = hb;
                hl[ci] = __float2bfloat16(hv - __bfloat162float(hb));
            }

            goal += NCTA;
            grid_barrier(goal);
        }
    }
}

// ---------------- final FC ----------------
__global__ void fc_kernel(const float* __restrict__ fc_w, const float* __restrict__ fc_b,
                          float* __restrict__ out) {
    int warp = (blockIdx.x * blockDim.x + threadIdx.x) >> 5;
    int lane = threadIdx.x & 31;
    if (warp >= BB * TT) return;
    int b = warp / TT;
    int t = warp - b * TT;
    size_t base = (size_t)t * BH + (size_t)b * HH;
    float s = 0.0f;
#pragma unroll 4
    for (int j = lane; j < HH; j += 32)
        s += (__bfloat162float(g_h2h[base + j]) + __bfloat162float(g_h2l[base + j])) * fc_w[j];
#pragma unroll
    for (int o = 16; o; o >>= 1) s += __shfl_xor_sync(0xFFFFFFFFu, s, o);
    if (lane == 0) out[warp] = s + fc_b[0];
}

// ---------------- launch ----------------
extern "C" void kernel_launch(void* const* d_in, const int* in_sizes, int n_in,
                              void* d_out, int out_size) {
    const float* inputs = (const float*)d_in[0];
    const float* W1 = (const float*)d_in[1];
    const float* U1 = (const float*)d_in[2];
    const float* V1 = (const float*)d_in[3];
    const float* b1 = (const float*)d_in[4];
    const float* W2 = (const float*)d_in[5];
    const float* U2 = (const float*)d_in[6];
    const float* V2 = (const float*)d_in[7];
    const float* b2 = (const float*)d_in[8];
    const float* fc_w = (const float*)d_in[9];
    const float* fc_b = (const float*)d_in[10];
    float* out = (float*)d_out;

    cudaFuncSetAttribute(lstm_kernel, cudaFuncAttributeMaxDynamicSharedMemorySize, SMEM_TOTAL);

    prep_kernel<<<(HH * GG + 255) / 256, 256>>>(W1, U1, V1, b1, W2, U2, V2, b2);

    dim3 grid(GG / 64, BB / 64);   // (32, 8) = 256 CTAs, all co-resident at 2/SM
    lstm_kernel<<<grid, 128, SMEM_TOTAL>>>(inputs);

    int nwarps = BB * TT;
    fc_kernel<<<(nwarps * 32 + 255) / 256, 256>>>(fc_w, fc_b, out);
}